// round 5
// baseline (speedup 1.0000x reference)
#include <cuda_runtime.h>
#include <cstdint>

#define NROWS 8192
#define NCOLS 2048
#define ORDER 8
#define NB    296
#define TPB   512
#define MAXR  28

typedef unsigned long long ull;

// ---------- packed-f32 primitives (FFMA2 on sm_103a is PTX-only) ----------
__device__ __forceinline__ ull pack2(float lo, float hi) {
    ull r; asm("mov.b64 %0, {%1, %2};" : "=l"(r) : "f"(lo), "f"(hi)); return r;
}
__device__ __forceinline__ float2 unpack2(ull v) {
    float2 f; asm("mov.b64 {%0, %1}, %2;" : "=f"(f.x), "=f"(f.y) : "l"(v)); return f;
}
__device__ __forceinline__ ull ffma2(ull a, ull b, ull c) {
    ull d; asm("fma.rn.f32x2 %0, %1, %2, %3;" : "=l"(d) : "l"(a), "l"(b), "l"(c)); return d;
}
__device__ __forceinline__ ull fmul2(ull a, ull b) {
    ull d; asm("mul.rn.f32x2 %0, %1, %2;" : "=l"(d) : "l"(a), "l"(b)); return d;
}

__global__ void __launch_bounds__(TPB, 2) orth_fused(
    const float* __restrict__ x, const float* __restrict__ v,
    const float* __restrict__ d, const float* __restrict__ bias,
    float* __restrict__ y)
{
    __shared__ float asum[16 * MAXR * 8];   // [warp][row][k]  14336 B
    __shared__ float bsh2[MAXR * 8 * 2];    // duplicated (b,b) pairs
    __shared__ float Tneg[64];              // -(rn_i T_ik rn_k)
    __shared__ float gpart[16 * 36];        // per-warp Gram partials

    const int t = threadIdx.x, lane = t & 31, w = t >> 5;
    const int c0 = t * 4;

    // ---- V slice: packed-only (32 regs), never kept as float4 ----
    ull V01[ORDER], V23[ORDER];
#pragma unroll
    for (int k = 0; k < ORDER; ++k) {
        const float4 vv = *reinterpret_cast<const float4*>(v + k * NCOLS + c0);
        V01[k] = pack2(vv.x, vv.y);
        V23[k] = pack2(vv.z, vv.w);
    }

    // ================= Prologue: Gram -> Tneg (tiny live set) =============
    {
        int idx = 0;
#pragma unroll
        for (int i = 0; i < ORDER; ++i) {
#pragma unroll
            for (int k = i; k < ORDER; ++k) {
                ull g2 = fmul2(V01[i], V01[k]);
                g2 = ffma2(V23[i], V23[k], g2);
                const float2 f = unpack2(g2);
                float g = f.x + f.y;
#pragma unroll
                for (int m = 16; m >= 1; m >>= 1)
                    g += __shfl_xor_sync(0xffffffffu, g, m);
                if (lane == 0) gpart[w * 36 + idx] = g;
                ++idx;
            }
        }
    }
    __syncthreads();
    if (t < 36) {
        float s = 0.f;
#pragma unroll
        for (int ww = 0; ww < 16; ++ww) s += gpart[ww * 36 + t];
        gpart[t] = s;   // column t only touched by thread t
    }
    __syncthreads();
    if (t == 0) {
        float Gs[ORDER][ORDER];
        int id2 = 0;
        for (int i = 0; i < ORDER; ++i)
            for (int k = i; k < ORDER; ++k) {
                Gs[i][k] = gpart[id2]; Gs[k][i] = gpart[id2]; ++id2;
            }
        float rn[ORDER];
        for (int i = 0; i < ORDER; ++i) rn[i] = 1.0f / sqrtf(Gs[i][i]);
        float T[ORDER][ORDER];
        for (int i = 0; i < ORDER; ++i)
            for (int k = 0; k < ORDER; ++k) T[i][k] = 0.f;
        for (int i = 0; i < ORDER; ++i) T[i][i] = 2.f;
        for (int c = 1; c < ORDER; ++c)
            for (int r = 0; r < c; ++r) {
                float s = 0.f;
                for (int m = r; m < c; ++m)
                    s += T[r][m] * (Gs[m][c] * rn[m] * rn[c]);
                T[r][c] = -2.f * s;
            }
        for (int i = 0; i < ORDER; ++i)
            for (int k = 0; k < ORDER; ++k)
                Tneg[i * 8 + k] = -(rn[i] * T[i][k] * rn[k]);
    }

    // ---- row range: 296 blocks, 27-28 rows each (single wave, 2/SM) ----
    const int bid = blockIdx.x;
    const int nr = (bid < 200) ? 28 : 27;
    const int r0 = (bid < 200) ? bid * 28 : 200 * 28 + (bid - 200) * 27;
    const float* xp = x + c0;

    // ================= Pass A: dot partials, no per-row barriers ==========
#pragma unroll 2
    for (int j = 0; j < nr; ++j) {
        const float4 xv = *reinterpret_cast<const float4*>(xp + (size_t)(r0 + j) * NCOLS);
        const ull x01 = pack2(xv.x, xv.y);
        const ull x23 = pack2(xv.z, xv.w);
        float p[8];
#pragma unroll
        for (int k = 0; k < 8; ++k) {
            const float2 f = unpack2(ffma2(x01, V01[k], fmul2(x23, V23[k])));
            p[k] = f.x + f.y;
        }
        // folded butterfly: 23 shfl; lanes 0..7 end with total for k = lane
#pragma unroll
        for (int k = 0; k < 8; ++k) {
            p[k] += __shfl_xor_sync(0xffffffffu, p[k], 16);
            p[k] += __shfl_xor_sync(0xffffffffu, p[k], 8);
        }
        {
            const bool h4 = (lane & 4) != 0;
            float q[4];
#pragma unroll
            for (int jj = 0; jj < 4; ++jj) {
                float keep = h4 ? p[jj + 4] : p[jj];
                float send = h4 ? p[jj] : p[jj + 4];
                q[jj] = keep + __shfl_xor_sync(0xffffffffu, send, 4);
            }
            const bool h2 = (lane & 2) != 0;
            float r2[2];
#pragma unroll
            for (int jj = 0; jj < 2; ++jj) {
                float keep = h2 ? q[jj + 2] : q[jj];
                float send = h2 ? q[jj] : q[jj + 2];
                r2[jj] = keep + __shfl_xor_sync(0xffffffffu, send, 2);
            }
            const bool h1 = (lane & 1) != 0;
            float keep = h1 ? r2[1] : r2[0];
            float send = h1 ? r2[0] : r2[1];
            float s = keep + __shfl_xor_sync(0xffffffffu, send, 1);
            if (lane < 8) asum[(w * MAXR + j) * 8 + lane] = s;
        }
    }

    // d/bias loads issued here so their latency overlaps the barrier
    const float4 dv = *reinterpret_cast<const float4*>(d + c0);
    const float4 bv = *reinterpret_cast<const float4*>(bias + c0);
    const ull d01 = pack2(dv.x, dv.y), d23 = pack2(dv.z, dv.w);
    const ull b01 = pack2(bv.x, bv.y), b23 = pack2(bv.z, bv.w);
    __syncthreads();

    // ================= Pass B: cross-warp reduce + T' (7 full warps) ======
    if (t < MAXR * 8) {
        const int row = t >> 3, k = t & 7;
        const int rowc = (row < nr) ? row : 0;     // keep all lanes shfl-active
        float a = 0.f;
#pragma unroll
        for (int ww = 0; ww < 16; ++ww) a += asum[(ww * MAXR + rowc) * 8 + k];
        float bk = 0.f;
#pragma unroll
        for (int i = 0; i < 8; ++i) {
            const float ai = __shfl_sync(0xffffffffu, a, (lane & 24) | i);
            bk = fmaf(ai, Tneg[i * 8 + k], bk);
        }
        if (row < nr) {
            bsh2[(row * 8 + k) * 2]     = bk;   // duplicated pair for LDS.64
            bsh2[(row * 8 + k) * 2 + 1] = bk;
        }
    }
    __syncthreads();

    // ================= Pass C: correction + scale + store =================
    float* yp = y + c0;
#pragma unroll 4
    for (int j = 0; j < nr; ++j) {
        const float4 xv = *reinterpret_cast<const float4*>(xp + (size_t)(r0 + j) * NCOLS);
        ull a01 = pack2(xv.x, xv.y);
        ull a23 = pack2(xv.z, xv.w);
#pragma unroll
        for (int k = 0; k < 8; ++k) {
            // broadcast LDS.64 of duplicated (b,b); Tneg already carries minus
            const ull bb = *reinterpret_cast<const ull*>(&bsh2[(j * 8 + k) * 2]);
            a01 = ffma2(bb, V01[k], a01);
            a23 = ffma2(bb, V23[k], a23);
        }
        a01 = ffma2(a01, d01, b01);
        a23 = ffma2(a23, d23, b23);
        const float2 o0 = unpack2(a01), o1 = unpack2(a23);
        __stcs(reinterpret_cast<float4*>(yp + (size_t)(r0 + j) * NCOLS),
               make_float4(o0.x, o0.y, o1.x, o1.y));
    }
}

extern "C" void kernel_launch(void* const* d_in, const int* in_sizes, int n_in,
                              void* d_out, int out_size) {
    const float* x    = (const float*)d_in[0];
    const float* v    = (const float*)d_in[1];
    const float* dvec = (const float*)d_in[2];
    const float* bias = (const float*)d_in[3];
    float* y = (float*)d_out;
    (void)in_sizes; (void)n_in; (void)out_size;

    orth_fused<<<NB, TPB>>>(x, v, dvec, bias, y);
}

// round 7
// speedup vs baseline: 1.4626x; 1.4626x over previous
#include <cuda_runtime.h>
#include <cstdint>

#define NROWS 8192
#define NCOLS 2048
#define ORDER 8
#define NB    148
#define TPB   512
#define MAXG  28    // max rows per group

typedef unsigned long long ull;

__device__ __forceinline__ ull pack2(float lo, float hi) {
    ull r; asm("mov.b64 %0, {%1, %2};" : "=l"(r) : "f"(lo), "f"(hi)); return r;
}
__device__ __forceinline__ float2 unpack2(ull v) {
    float2 f; asm("mov.b64 {%0, %1}, %2;" : "=f"(f.x), "=f"(f.y) : "l"(v)); return f;
}
__device__ __forceinline__ ull ffma2(ull a, ull b, ull c) {
    ull d; asm("fma.rn.f32x2 %0, %1, %2, %3;" : "=l"(d) : "l"(a), "l"(b), "l"(c)); return d;
}
__device__ __forceinline__ ull fmul2(ull a, ull b) {
    ull d; asm("mul.rn.f32x2 %0, %1, %2;" : "=l"(d) : "l"(a), "l"(b)); return d;
}
__device__ __forceinline__ void barg(int id) {
    asm volatile("bar.sync %0, 256;" :: "r"(id) : "memory");
}

__global__ void __launch_bounds__(TPB, 1) orth_fused(
    const float* __restrict__ x, const float* __restrict__ v,
    const float* __restrict__ d, const float* __restrict__ bias,
    float* __restrict__ y)
{
    __shared__ float asum[16 * MAXG * 8];     // [warp][rowInGroup][k]
    __shared__ float bsh2[2 * MAXG * 8 * 2];  // per-group duplicated (b,b)
    __shared__ float Tneg[64];
    __shared__ float gpart[16 * 36];

    const int t = threadIdx.x, lane = t & 31, w = t >> 5;
    const int g = w >> 3, wg = w & 7;             // group 0/1, warp-in-group
    const int colA = wg * 256 + lane * 4;          // two coalesced regions
    const int colB = colA + 128;

    // ---- V slice: 8 cols/thread, packed f32x2 only ----
    ull VA0[ORDER], VA1[ORDER], VB0[ORDER], VB1[ORDER];
#pragma unroll
    for (int k = 0; k < ORDER; ++k) {
        const float4 a = *reinterpret_cast<const float4*>(v + k * NCOLS + colA);
        const float4 b = *reinterpret_cast<const float4*>(v + k * NCOLS + colB);
        VA0[k] = pack2(a.x, a.y); VA1[k] = pack2(a.z, a.w);
        VB0[k] = pack2(b.x, b.y); VB1[k] = pack2(b.z, b.w);
    }

    // ================= Prologue: Gram -> Tneg =================
    {
        int idx = 0;
#pragma unroll
        for (int i = 0; i < ORDER; ++i) {
#pragma unroll
            for (int k = i; k < ORDER; ++k) {
                ull g2 = fmul2(VA0[i], VA0[k]);
                g2 = ffma2(VA1[i], VA1[k], g2);
                g2 = ffma2(VB0[i], VB0[k], g2);
                g2 = ffma2(VB1[i], VB1[k], g2);
                const float2 f = unpack2(g2);
                float gg = f.x + f.y;
#pragma unroll
                for (int m = 16; m >= 1; m >>= 1)
                    gg += __shfl_xor_sync(0xffffffffu, gg, m);
                if (lane == 0) gpart[w * 36 + idx] = gg;
                ++idx;
            }
        }
    }
    __syncthreads();
    if (t < 36) {
        float s = 0.f;
#pragma unroll
        for (int ww = 0; ww < 16; ++ww) s += gpart[ww * 36 + t];
        // groups 0 and 1 cover the SAME columns -> 16-warp sum double-counts
        gpart[t] = 0.5f * s;
    }
    __syncthreads();
    if (t == 0) {
        float Gs[ORDER][ORDER];
        int id2 = 0;
        for (int i = 0; i < ORDER; ++i)
            for (int k = i; k < ORDER; ++k) {
                Gs[i][k] = gpart[id2]; Gs[k][i] = gpart[id2]; ++id2;
            }
        float rn[ORDER];
        for (int i = 0; i < ORDER; ++i) rn[i] = 1.0f / sqrtf(Gs[i][i]);
        float T[ORDER][ORDER];
        for (int i = 0; i < ORDER; ++i)
            for (int k = 0; k < ORDER; ++k) T[i][k] = 0.f;
        for (int i = 0; i < ORDER; ++i) T[i][i] = 2.f;
        for (int c = 1; c < ORDER; ++c)
            for (int r = 0; r < c; ++r) {
                float s = 0.f;
                for (int m = r; m < c; ++m)
                    s += T[r][m] * (Gs[m][c] * rn[m] * rn[c]);
                T[r][c] = -2.f * s;
            }
        for (int i = 0; i < ORDER; ++i)
            for (int k = 0; k < ORDER; ++k)
                Tneg[i * 8 + k] = -(rn[i] * T[i][k] * rn[k]);
    }
    __syncthreads();   // last full-block barrier; groups decouple below

    // ---- rows: 148 blocks; group g takes rows r0 + 2j + g ----
    const int bid = blockIdx.x;
    const int nr = (bid < 52) ? 56 : 55;
    const int r0 = (bid < 52) ? bid * 56 : 52 * 56 + (bid - 52) * 55;
    const int ng = (nr - g + 1) >> 1;          // 28 or 27

    // ================= Pass A: dot partials (8 warps per row) =============
#pragma unroll 2
    for (int j = 0; j < ng; ++j) {
        const size_t roff = (size_t)(r0 + 2 * j + g) * NCOLS;
        const float4 xa = *reinterpret_cast<const float4*>(x + roff + colA);
        const float4 xb = *reinterpret_cast<const float4*>(x + roff + colB);
        const ull x01 = pack2(xa.x, xa.y), x23 = pack2(xa.z, xa.w);
        const ull x45 = pack2(xb.x, xb.y), x67 = pack2(xb.z, xb.w);
        float p[8];
#pragma unroll
        for (int k = 0; k < 8; ++k) {
            ull s2 = fmul2(x01, VA0[k]);
            s2 = ffma2(x23, VA1[k], s2);
            s2 = ffma2(x45, VB0[k], s2);
            s2 = ffma2(x67, VB1[k], s2);
            const float2 f = unpack2(s2);
            p[k] = f.x + f.y;
        }
        // folded butterfly: 23 shfl; lanes 0..7 end with total for k = lane
#pragma unroll
        for (int k = 0; k < 8; ++k) {
            p[k] += __shfl_xor_sync(0xffffffffu, p[k], 16);
            p[k] += __shfl_xor_sync(0xffffffffu, p[k], 8);
        }
        {
            const bool h4 = (lane & 4) != 0;
            float q[4];
#pragma unroll
            for (int jj = 0; jj < 4; ++jj) {
                float keep = h4 ? p[jj + 4] : p[jj];
                float send = h4 ? p[jj] : p[jj + 4];
                q[jj] = keep + __shfl_xor_sync(0xffffffffu, send, 4);
            }
            const bool h2 = (lane & 2) != 0;
            float r2[2];
#pragma unroll
            for (int jj = 0; jj < 2; ++jj) {
                float keep = h2 ? q[jj + 2] : q[jj];
                float send = h2 ? q[jj] : q[jj + 2];
                r2[jj] = keep + __shfl_xor_sync(0xffffffffu, send, 2);
            }
            const bool h1 = (lane & 1) != 0;
            float keep = h1 ? r2[1] : r2[0];
            float send = h1 ? r2[0] : r2[1];
            float s = keep + __shfl_xor_sync(0xffffffffu, send, 1);
            if (lane < 8) asum[w * (MAXG * 8) + j * 8 + lane] = s;
        }
    }

    // d/bias loads overlap the barrier
    const float4 da = *reinterpret_cast<const float4*>(d + colA);
    const float4 db = *reinterpret_cast<const float4*>(d + colB);
    const float4 ba = *reinterpret_cast<const float4*>(bias + colA);
    const float4 bb4 = *reinterpret_cast<const float4*>(bias + colB);
    const ull dA0 = pack2(da.x, da.y), dA1 = pack2(da.z, da.w);
    const ull dB0 = pack2(db.x, db.y), dB1 = pack2(db.z, db.w);
    const ull bA0 = pack2(ba.x, ba.y), bA1 = pack2(ba.z, ba.w);
    const ull bB0 = pack2(bb4.x, bb4.y), bB1 = pack2(bb4.z, bb4.w);

    barg(1 + g);

    // ================= Pass B: 7 warps per group, all lanes active ========
    {
        const int tl = t & 255;
        if (tl < MAXG * 8) {                       // 224 = 7 full warps
            const int row = tl >> 3, k = tl & 7;
            const int rowc = (row < ng) ? row : 0; // clamp, keep shfl full
            float a = 0.f;
#pragma unroll
            for (int ww = 0; ww < 8; ++ww)
                a += asum[(g * 8 + ww) * (MAXG * 8) + rowc * 8 + k];
            float bk = 0.f;
#pragma unroll
            for (int i = 0; i < 8; ++i) {
                const float ai = __shfl_sync(0xffffffffu, a, (lane & 24) | i);
                bk = fmaf(ai, Tneg[i * 8 + k], bk);
            }
            if (row < ng) {
                const int o = (g * MAXG * 8 + row * 8 + k) * 2;
                bsh2[o] = bk; bsh2[o + 1] = bk;
            }
        }
    }
    barg(1 + g);

    // ================= Pass C: correction + scale + store =================
#pragma unroll 2
    for (int j = 0; j < ng; ++j) {
        const size_t roff = (size_t)(r0 + 2 * j + g) * NCOLS;
        const float4 xa = *reinterpret_cast<const float4*>(x + roff + colA);
        const float4 xb = *reinterpret_cast<const float4*>(x + roff + colB);
        ull a01 = pack2(xa.x, xa.y), a23 = pack2(xa.z, xa.w);
        ull a45 = pack2(xb.x, xb.y), a67 = pack2(xb.z, xb.w);
#pragma unroll
        for (int k = 0; k < 8; ++k) {
            const ull bb = *reinterpret_cast<const ull*>(
                &bsh2[(g * MAXG * 8 + j * 8 + k) * 2]);
            a01 = ffma2(bb, VA0[k], a01);
            a23 = ffma2(bb, VA1[k], a23);
            a45 = ffma2(bb, VB0[k], a45);
            a67 = ffma2(bb, VB1[k], a67);
        }
        a01 = ffma2(a01, dA0, bA0);
        a23 = ffma2(a23, dA1, bA1);
        a45 = ffma2(a45, dB0, bB0);
        a67 = ffma2(a67, dB1, bB1);
        const float2 o0 = unpack2(a01), o1 = unpack2(a23);
        const float2 o2 = unpack2(a45), o3 = unpack2(a67);
        __stcs(reinterpret_cast<float4*>(y + roff + colA),
               make_float4(o0.x, o0.y, o1.x, o1.y));
        __stcs(reinterpret_cast<float4*>(y + roff + colB),
               make_float4(o2.x, o2.y, o3.x, o3.y));
    }
}

extern "C" void kernel_launch(void* const* d_in, const int* in_sizes, int n_in,
                              void* d_out, int out_size) {
    const float* x    = (const float*)d_in[0];
    const float* v    = (const float*)d_in[1];
    const float* dvec = (const float*)d_in[2];
    const float* bias = (const float*)d_in[3];
    float* y = (float*)d_out;
    (void)in_sizes; (void)n_in; (void)out_size;

    orth_fused<<<NB, TPB>>>(x, v, dvec, bias, y);
}